// round 2
// baseline (speedup 1.0000x reference)
#include <cuda_runtime.h>
#include <math.h>

#define CIN 64
#define COUT_PER 32
#define LALPHA 0.2f

// ---------------- static device scratch (no allocations allowed) ----------------
// D tables (forward DFT) and C tables (inverse DFT), per fft, packed:
//   off: fft32 -> 0 (34*32=1088), fft64 -> 1088 (66*64=4224), fft128 -> 5312 (130*128=16640)
__device__ float g_D[21952];
__device__ float g_C[21952];
// Combined per-bin weights G[k][j=ri*64+c][o2=2o+rio], 128x64 per bin, 115 bins
//   off: fft32 -> 0, fft64 -> 17*8192=139264, fft128 -> 50*8192=409600
__device__ float g_G[942080];
// X[k][f][ri][c]  (per fft): sizes 17*2048*128, 33*1024*128, 65*512*128
//   off: 0, 4456448, 8781824 ; total 13041664 floats (~50 MB)
__device__ float g_X[13041664];
// Z[f][k][ri][o] (per fft): sizes 2048*17*64, 1024*33*64, 512*65*64
//   off: 0, 2228224, 4390912 ; total 6520832 floats (~25 MB)
__device__ float g_Z[6520832];

__device__ __forceinline__ float lk(float v) { return v > 0.f ? v : LALPHA * v; }

// ---------------- precompute: DFT / iDFT tables ----------------
__global__ void k_build_dft() {
    int ffti = blockIdx.y;
    int N = 32 << ffti;
    int bins = N / 2 + 1;
    int R = 2 * bins;
    int total = R * N;
    int off = (ffti == 0) ? 0 : (ffti == 1 ? 1088 : 5312);
    int stride = gridDim.x * blockDim.x;
    for (int idx = blockIdx.x * blockDim.x + threadIdx.x; idx < total; idx += stride) {
        // D layout [r][t], r = 2k+ri
        {
            int r = idx / N, t = idx % N;
            int k = r >> 1, ri = r & 1;
            int m = (k * t) % N;
            float s, c;
            sincospif(2.0f * (float)m / (float)N, &s, &c);
            g_D[off + idx] = ri ? -s : c;
        }
        // C layout [t][j], j = 2k+ri
        {
            int t = idx / R, j = idx % R;
            int k = j >> 1, ri = j & 1;
            int m = (k * t) % N;
            float s, c;
            sincospif(2.0f * (float)m / (float)N, &s, &c);
            float w = (k == 0 || k == bins - 1) ? 1.0f : 2.0f;
            g_C[off + idx] = (ri ? -s : c) * (w / (float)N);
        }
    }
}

// ---------------- precompute: resized kernels -> combined G matrices ----------------
__global__ void k_build_G(const float* __restrict__ kr, const float* __restrict__ ki) {
    int ffti = blockIdx.y;
    int N = 32 << ffti;
    int bins = N / 2 + 1;
    int goff = (ffti == 0) ? 0 : (ffti == 1 ? 139264 : 409600);
    int total = bins * CIN * COUT_PER;
    int stride = gridDim.x * blockDim.x;
    for (int idx = blockIdx.x * blockDim.x + threadIdx.x; idx < total; idx += stride) {
        int k = idx / (CIN * COUT_PER);
        int rem = idx % (CIN * COUT_PER);   // = c*32 + o, matches kernel last-dim layout
        int c = rem / COUT_PER, o = rem % COUT_PER;
        float vr, vi;
        if (bins == 33) {
            vr = kr[k * 2048 + rem];
            vi = ki[k * 2048 + rem];
        } else {
            // jax.image.resize linear, antialias=False, half-pixel; boundary
            // renormalization == clamped lerp
            float src = (k + 0.5f) * (33.0f / (float)bins) - 0.5f;
            float fl = floorf(src);
            int i0 = (int)fl;
            float f = src - fl;
            int i0c = i0 < 0 ? 0 : i0;
            int i1c = i0 + 1 > 32 ? 32 : i0 + 1;
            vr = (1.0f - f) * kr[i0c * 2048 + rem] + f * kr[i1c * 2048 + rem];
            vi = (1.0f - f) * ki[i0c * 2048 + rem] + f * ki[i1c * 2048 + rem];
        }
        float* Gk = g_G + goff + k * 8192;
        // [Zr Zi] = [Xr Xi] * [[kr ki],[-ki kr]]
        Gk[c * 64 + 2 * o]            = vr;
        Gk[c * 64 + 2 * o + 1]        = vi;
        Gk[(64 + c) * 64 + 2 * o]     = -vi;
        Gk[(64 + c) * 64 + 2 * o + 1] = vr;
    }
}

// ---------------- stage 1: forward DFT, one CTA per frame ----------------
// out: X[k][f][ri][c] = sum_t D[2k+ri][t] * x[f*N+t][c]
template <int N, int DOFF, int XOFF, int F>
__global__ void k_stage1(const float* __restrict__ x) {
    constexpr int R = N + 2;
    constexpr int NIT = (R + 15) / 16;
    constexpr int RPAD = NIT * 16;
    extern __shared__ float sm[];
    float* D_s = sm;                       // RPAD x (N+1)
    float* x_s = sm + RPAD * (N + 1);      // N x 64
    const int tid = threadIdx.x;
    const int f = blockIdx.x;

    for (int idx = tid; idx < R * N; idx += 256) {
        int r = idx / N, t = idx % N;
        D_s[r * (N + 1) + t] = g_D[DOFF + idx];
    }
    for (int idx = tid; idx < (RPAD - R) * N; idx += 256) {
        int r = R + idx / N, t = idx % N;
        D_s[r * (N + 1) + t] = 0.0f;
    }
    const float4* xg = reinterpret_cast<const float4*>(x + (size_t)f * N * 64);
    float4* xs4 = reinterpret_cast<float4*>(x_s);
    for (int idx = tid; idx < N * 16; idx += 256) xs4[idx] = xg[idx];
    __syncthreads();

    const int ty = tid >> 4, tx = tid & 15;
    float acc[NIT][4];
#pragma unroll
    for (int i = 0; i < NIT; i++) { acc[i][0] = acc[i][1] = acc[i][2] = acc[i][3] = 0.f; }

#pragma unroll 4
    for (int t = 0; t < N; t++) {
        float4 b = xs4[t * 16 + tx];
#pragma unroll
        for (int i = 0; i < NIT; i++) {
            float a = D_s[(ty + 16 * i) * (N + 1) + t];
            acc[i][0] += a * b.x; acc[i][1] += a * b.y;
            acc[i][2] += a * b.z; acc[i][3] += a * b.w;
        }
    }
#pragma unroll
    for (int i = 0; i < NIT; i++) {
        int r = ty + 16 * i;
        if (r < R) {
            int k = r >> 1, ri = r & 1;
            float4* dst = reinterpret_cast<float4*>(
                g_X + XOFF + ((size_t)(k * F + f) * 2 + ri) * 64 + tx * 4);
            *dst = make_float4(acc[i][0], acc[i][1], acc[i][2], acc[i][3]);
        }
    }
}

// ---------------- stage 2: per-bin [64f x 128] x [128 x 64] GEMM + leaky ----------------
__global__ void k_stage2(int xoff, int goff, int zoff, int F, int bins) {
    extern __shared__ float sm[];
    float* A_s = sm;               // 64 x 132 (padded)
    float* B_s = sm + 64 * 132;    // 128 x 64
    const int tid = threadIdx.x;
    const int k = blockIdx.y;
    const int f0 = blockIdx.x * 64;

    const float4* Xg = reinterpret_cast<const float4*>(g_X + xoff + ((size_t)k * F + f0) * 128);
    for (int idx = tid; idx < 64 * 32; idx += 256) {
        int fl = idx >> 5, jq = idx & 31;
        reinterpret_cast<float4*>(A_s + fl * 132)[jq] = Xg[fl * 32 + jq];
    }
    const float4* Gg = reinterpret_cast<const float4*>(g_G + goff + (size_t)k * 8192);
    float4* B4 = reinterpret_cast<float4*>(B_s);
    for (int idx = tid; idx < 2048; idx += 256) B4[idx] = Gg[idx];
    __syncthreads();

    const int ty = tid >> 4, tx = tid & 15;
    float acc[4][4] = {};
#pragma unroll 4
    for (int j = 0; j < 128; j++) {
        float4 b = reinterpret_cast<const float4*>(B_s + j * 64)[tx];
#pragma unroll
        for (int i = 0; i < 4; i++) {
            float a = A_s[(4 * ty + i) * 132 + j];
            acc[i][0] += a * b.x; acc[i][1] += a * b.y;
            acc[i][2] += a * b.z; acc[i][3] += a * b.w;
        }
    }
#pragma unroll
    for (int i = 0; i < 4; i++) {
        int f = f0 + 4 * ty + i;
        float* zp = g_Z + zoff + ((size_t)f * bins + k) * 64;
        // col o2 = 4*tx + jj ; o = o2>>1 ; rio = o2&1
        reinterpret_cast<float2*>(zp)[tx]      = make_float2(lk(acc[i][0]), lk(acc[i][2])); // ri=0
        reinterpret_cast<float2*>(zp + 32)[tx] = make_float2(lk(acc[i][1]), lk(acc[i][3])); // ri=1
    }
}

// ---------------- stage 3: irfft per frame + bias, GG frames per CTA ----------------
template <int N, int GG, int COFF, int ZOFF, int OOFF, int F>
__global__ void k_stage3(float* __restrict__ out, const float* __restrict__ bias) {
    constexpr int BINS = N / 2 + 1;
    constexpr int R = 2 * BINS;
    constexpr int NR = N / 16;
    extern __shared__ float sm[];
    float* C_s = sm;                   // N x (R+1)
    float* Z_s = sm + N * (R + 1);     // BINS*64 = R*32
    const int tid = threadIdx.x;

    for (int idx = tid; idx < N * R; idx += 256) {
        int t = idx / R, j = idx % R;
        C_s[t * (R + 1) + j] = g_C[COFF + idx];
    }
    const int ty = tid >> 4, tx = tid & 15;
    const float2 bv = *reinterpret_cast<const float2*>(bias + OOFF + 2 * tx);

    for (int g = 0; g < GG; g++) {
        const int f = blockIdx.x * GG + g;
        __syncthreads();  // C_s ready / previous Z_s consumers done
        const float4* Zg = reinterpret_cast<const float4*>(g_Z + ZOFF + (size_t)f * BINS * 64);
        float4* Z4 = reinterpret_cast<float4*>(Z_s);
        for (int idx = tid; idx < BINS * 16; idx += 256) Z4[idx] = Zg[idx];
        __syncthreads();

        float acc[NR][2] = {};
#pragma unroll 2
        for (int j = 0; j < R; j++) {
            float2 b = reinterpret_cast<const float2*>(Z_s + j * 32)[tx];
#pragma unroll
            for (int i = 0; i < NR; i++) {
                float a = C_s[(ty + 16 * i) * (R + 1) + j];
                acc[i][0] += a * b.x;
                acc[i][1] += a * b.y;
            }
        }
#pragma unroll
        for (int i = 0; i < NR; i++) {
            int t = ty + 16 * i;
            *reinterpret_cast<float2*>(out + ((size_t)f * N + t) * 96 + OOFF + 2 * tx) =
                make_float2(acc[i][0] + bv.x, acc[i][1] + bv.y);
        }
    }
}

// ---------------- launch ----------------
extern "C" void kernel_launch(void* const* d_in, const int* in_sizes, int n_in,
                              void* d_out, int out_size) {
    const float* x    = (const float*)d_in[0];
    const float* kr   = (const float*)d_in[1];
    const float* ki   = (const float*)d_in[2];
    const float* bias = (const float*)d_in[3];
    float* out = (float*)d_out;

    // smem sizes
    const int s1_32  = (48 * 33 + 32 * 64) * 4;    // 14528
    const int s1_64  = (80 * 65 + 64 * 64) * 4;    // 37184
    const int s1_128 = (144 * 129 + 128 * 64) * 4; // 107072
    const int s2     = (64 * 132 + 128 * 64) * 4;  // 66560
    const int s3_32  = (32 * 35 + 17 * 64) * 4;    // 8832
    const int s3_64  = (64 * 67 + 33 * 64) * 4;    // 25600
    const int s3_128 = (128 * 131 + 65 * 64) * 4;  // 83712

    cudaFuncSetAttribute(k_stage1<128, 5312, 8781824, 512>,
                         cudaFuncAttributeMaxDynamicSharedMemorySize, s1_128);
    cudaFuncSetAttribute(k_stage2, cudaFuncAttributeMaxDynamicSharedMemorySize, s2);
    cudaFuncSetAttribute(k_stage3<128, 2, 5312, 4390912, 64, 512>,
                         cudaFuncAttributeMaxDynamicSharedMemorySize, s3_128);

    k_build_dft<<<dim3(65, 3), 256>>>();
    k_build_G<<<dim3(520, 3), 256>>>(kr, ki);

    k_stage1<32, 0, 0, 2048><<<2048, 256, s1_32>>>(x);
    k_stage1<64, 1088, 4456448, 1024><<<1024, 256, s1_64>>>(x);
    k_stage1<128, 5312, 8781824, 512><<<512, 256, s1_128>>>(x);

    k_stage2<<<dim3(32, 17), 256, s2>>>(0, 0, 0, 2048, 17);
    k_stage2<<<dim3(16, 33), 256, s2>>>(4456448, 139264, 2228224, 1024, 33);
    k_stage2<<<dim3(8, 65), 256, s2>>>(8781824, 409600, 4390912, 512, 65);

    k_stage3<32, 8, 0, 0, 0, 2048><<<256, 256, s3_32>>>(out, bias);
    k_stage3<64, 4, 1088, 2228224, 32, 1024><<<256, 256, s3_64>>>(out, bias);
    k_stage3<128, 2, 5312, 4390912, 64, 512><<<256, 256, s3_128>>>(out, bias);
}